// round 4
// baseline (speedup 1.0000x reference)
#include <cuda_runtime.h>
#include <cstdint>
#include <math.h>

// Problem constants
#define BB 4
#define NN 2048
#define DD 512
#define HH 8
#define HD 64
#define NC 2048
#define RR (BB*NN)

// Scratch (device globals; no allocation allowed)
__device__ float g_xn[(size_t)RR * DD];   // layernorm(x); reused for o_input
__device__ float g_mm[(size_t)RR * NC];   // silu(xn @ uvqk): [u | v | q | k]
__device__ float g_at[(size_t)RR * DD];   // attention output

__device__ __forceinline__ float silu_f(float v) {
    return v / (1.0f + __expf(-v));
}

__device__ __forceinline__ uint32_t smem_u32(const void* p) {
    uint32_t a;
    asm("{ .reg .u64 t; cvta.to.shared.u64 t, %1; cvt.u32.u64 %0, t; }"
        : "=r"(a) : "l"(p));
    return a;
}

__device__ __forceinline__ void ldmA(uint32_t* a, uint32_t addr) {
    asm volatile("ldmatrix.sync.aligned.m8n8.x4.shared.b16 {%0,%1,%2,%3}, [%4];"
                 : "=r"(a[0]), "=r"(a[1]), "=r"(a[2]), "=r"(a[3]) : "r"(addr));
}

__device__ __forceinline__ void mma_tf32(float* d, const uint32_t* a,
                                         uint32_t b0, uint32_t b1) {
    asm volatile(
        "mma.sync.aligned.m16n8k8.row.col.f32.tf32.tf32.f32 "
        "{%0,%1,%2,%3},{%4,%5,%6,%7},{%8,%9},{%0,%1,%2,%3};"
        : "+f"(d[0]), "+f"(d[1]), "+f"(d[2]), "+f"(d[3])
        : "r"(a[0]), "r"(a[1]), "r"(a[2]), "r"(a[3]), "r"(b0), "r"(b1));
}

__device__ __forceinline__ void cp16(uint32_t dst, const void* src) {
    asm volatile("cp.async.cg.shared.global [%0], [%1], 16;" :: "r"(dst), "l"(src));
}
#define CP_COMMIT() asm volatile("cp.async.commit_group;" ::: "memory")
#define CP_WAIT(n)  asm volatile("cp.async.wait_group %0;" :: "n"(n) : "memory")

// per-thread ldmatrix-x4 byte offset for A-fragment, row stride = sa floats
__device__ __forceinline__ uint32_t ldm_off(int lane, int sa_floats) {
    int r = (lane & 7) + ((lane >> 3) & 1) * 8;
    int c16 = (lane >> 4);
    return (uint32_t)(r * sa_floats * 4 + c16 * 16);
}

// ---------------------------------------------------------------------------
// LayerNorm kernels (known-good)
// ---------------------------------------------------------------------------
__global__ void ln_kernel(const float* __restrict__ x) {
    int row = blockIdx.x;
    int t = threadIdx.x;
    float4 v = ((const float4*)(x + (size_t)row * DD))[t];
    float s  = v.x + v.y + v.z + v.w;
    float s2 = v.x*v.x + v.y*v.y + v.z*v.z + v.w*v.w;
#pragma unroll
    for (int o = 16; o > 0; o >>= 1) {
        s  += __shfl_xor_sync(0xffffffffu, s,  o);
        s2 += __shfl_xor_sync(0xffffffffu, s2, o);
    }
    __shared__ float sh[8];
    if ((t & 31) == 0) { sh[t >> 5] = s; sh[4 + (t >> 5)] = s2; }
    __syncthreads();
    s  = sh[0] + sh[1] + sh[2] + sh[3];
    s2 = sh[4] + sh[5] + sh[6] + sh[7];
    float mu  = s * (1.0f / DD);
    float var = fmaxf(s2 * (1.0f / DD) - mu * mu, 0.0f);
    float r   = rsqrtf(var + 1e-6f);
    float4 o;
    o.x = (v.x - mu) * r; o.y = (v.y - mu) * r;
    o.z = (v.z - mu) * r; o.w = (v.w - mu) * r;
    ((float4*)(g_xn + (size_t)row * DD))[t] = o;
}

__global__ void gated_ln_kernel() {
    int row = blockIdx.x;
    int t = threadIdx.x;
    float4 v = ((const float4*)(g_at + (size_t)row * DD))[t];
    float s  = v.x + v.y + v.z + v.w;
    float s2 = v.x*v.x + v.y*v.y + v.z*v.z + v.w*v.w;
#pragma unroll
    for (int o = 16; o > 0; o >>= 1) {
        s  += __shfl_xor_sync(0xffffffffu, s,  o);
        s2 += __shfl_xor_sync(0xffffffffu, s2, o);
    }
    __shared__ float sh[8];
    if ((t & 31) == 0) { sh[t >> 5] = s; sh[4 + (t >> 5)] = s2; }
    __syncthreads();
    s  = sh[0] + sh[1] + sh[2] + sh[3];
    s2 = sh[4] + sh[5] + sh[6] + sh[7];
    float mu  = s * (1.0f / DD);
    float var = fmaxf(s2 * (1.0f / DD) - mu * mu, 0.0f);
    float r   = rsqrtf(var + 1e-6f);
    float4 u = ((const float4*)(g_mm + (size_t)row * NC))[t];
    float4 o;
    o.x = u.x * (v.x - mu) * r; o.y = u.y * (v.y - mu) * r;
    o.z = u.z * (v.z - mu) * r; o.w = u.w * (v.w - mu) * r;
    ((float4*)(g_xn + (size_t)row * DD))[t] = o;
}

// ---------------------------------------------------------------------------
// tf32 mma.sync GEMM (unchanged from round 3, known-good)
// ---------------------------------------------------------------------------
#define SA  36
#define ASB (128 * SA * 4)
#define SB0 136
#define BSB0 (32 * SB0 * 4)
#define SB1 36
#define BSB1 (128 * SB1 * 4)
#define GSMEM (2 * ASB + 2 * BSB1)

template <int MODE>
__global__ __launch_bounds__(256)
void gemm_mma(const float* __restrict__ A, const float* __restrict__ Bm,
              float* __restrict__ C, const float* __restrict__ bias,
              const float* __restrict__ xres, int Nn, int K) {
    extern __shared__ char smem[];
    const int BSB = (MODE == 0) ? BSB0 : BSB1;
    char* sB = smem + 2 * ASB;
    uint32_t sAu = smem_u32(smem);
    uint32_t sBu = smem_u32(sB);

    int tid = threadIdx.x;
    int wid = tid >> 5, lane = tid & 31;
    int m0 = blockIdx.y * 128, n0 = blockIdx.x * 128;
    int wm = (wid & 1) * 64;
    int wn = (wid >> 1) * 32;

    float acc[4][4][4];
#pragma unroll
    for (int i = 0; i < 4; i++)
#pragma unroll
        for (int j = 0; j < 4; j++)
#pragma unroll
            for (int r = 0; r < 4; r++) acc[i][j][r] = 0.0f;

    const int NCH = K / 32;
    uint32_t aoff = ldm_off(lane, SA);

    auto stageA = [&](int c, int s) {
#pragma unroll
        for (int i = 0; i < 4; i++) {
            int idx = tid + i * 256;
            int row = idx >> 3, seg = idx & 7;
            cp16(sAu + s * ASB + (row * SA + seg * 4) * 4,
                 A + (size_t)(m0 + row) * K + c * 32 + seg * 4);
        }
    };
    auto stageB = [&](int c, int s) {
        if (MODE == 0) {
#pragma unroll
            for (int i = 0; i < 4; i++) {
                int idx = tid + i * 256;
                int row = idx >> 5, seg = idx & 31;
                cp16(sBu + s * BSB + (row * SB0 + seg * 4) * 4,
                     Bm + (size_t)(c * 32 + row) * Nn + n0 + seg * 4);
            }
        } else {
#pragma unroll
            for (int i = 0; i < 4; i++) {
                int idx = tid + i * 256;
                int row = idx >> 3, seg = idx & 7;
                cp16(sBu + s * BSB + (row * SB1 + seg * 4) * 4,
                     Bm + (size_t)(n0 + row) * K + c * 32 + seg * 4);
            }
        }
    };

    stageA(0, 0); stageB(0, 0); CP_COMMIT();

    for (int c = 0; c < NCH; c++) {
        int s = c & 1;
        if (c + 1 < NCH) {
            stageA(c + 1, s ^ 1); stageB(c + 1, s ^ 1); CP_COMMIT();
            CP_WAIT(1);
        } else {
            CP_WAIT(0);
        }
        __syncthreads();

        const float* Bsf = (const float*)(sB + s * BSB);
#pragma unroll
        for (int ks = 0; ks < 4; ks++) {
            uint32_t bf[4][2];
#pragma unroll
            for (int in = 0; in < 4; in++) {
                int nn = wn + in * 8 + lane / 4;
                int kk = ks * 8 + (lane & 3);
                if (MODE == 0) {
                    bf[in][0] = __float_as_uint(Bsf[kk * SB0 + nn]);
                    bf[in][1] = __float_as_uint(Bsf[(kk + 4) * SB0 + nn]);
                } else {
                    bf[in][0] = __float_as_uint(Bsf[nn * SB1 + kk]);
                    bf[in][1] = __float_as_uint(Bsf[nn * SB1 + kk + 4]);
                }
            }
#pragma unroll
            for (int im = 0; im < 4; im++) {
                uint32_t a[4];
                ldmA(a, sAu + s * ASB + (uint32_t)(((wm + im * 16) * SA + ks * 8) * 4) + aoff);
#pragma unroll
                for (int in = 0; in < 4; in++)
                    mma_tf32(acc[im][in], a, bf[in][0], bf[in][1]);
            }
        }
        __syncthreads();
    }

    int er = lane >> 2, ec = (lane & 3) * 2;
#pragma unroll
    for (int im = 0; im < 4; im++) {
#pragma unroll
        for (int in = 0; in < 4; in++) {
            int row = m0 + wm + im * 16 + er;
            int col = n0 + wn + in * 8 + ec;
#pragma unroll
            for (int h = 0; h < 2; h++) {
                float v0 = acc[im][in][2 * h + 0];
                float v1 = acc[im][in][2 * h + 1];
                int rr = row + 8 * h;
                if (MODE == 0) {
                    float2 o; o.x = silu_f(v0); o.y = silu_f(v1);
                    *(float2*)(C + (size_t)rr * Nn + col) = o;
                } else {
                    float2 bi = *(const float2*)(bias + col);
                    float2 xr = *(const float2*)(xres + (size_t)rr * Nn + col);
                    float2 o; o.x = v0 + bi.x + xr.x; o.y = v1 + bi.y + xr.y;
                    *(float2*)(C + (size_t)rr * Nn + col) = o;
                }
            }
        }
    }
}

// ---------------------------------------------------------------------------
// Fused causal silu-attention, round 4:
// Q-tile 128 x KV-tile 64, 8 warps (4m x 2n), warp tile 32x32.
// cp.async double-buffered K/V. S staged via smem (Ss) for the second mma.
// For q-tile qt there are 2qt+2 kv tiles; last two need the causal mask.
// ---------------------------------------------------------------------------
#define SAT 68
#define QTILE (128 * SAT * 4)          // 34816
#define KTILE (64 * SAT * 4)           // 17408
// layout: Qs | Ks[2] | Vs[2] | Ss
#define OFF_K  QTILE
#define OFF_V  (QTILE + 2 * KTILE)
#define OFF_S  (QTILE + 4 * KTILE)
#define ASMEM  (QTILE + 4 * KTILE + QTILE)   // 139264

__global__ __launch_bounds__(256, 1)
void attn_mma() {
    extern __shared__ char smem[];
    float* Qs = (float*)smem;
    float* Ss = (float*)(smem + OFF_S);
    uint32_t sbase = smem_u32(smem);
    uint32_t Qsu = sbase;
    uint32_t Ssu = sbase + OFF_S;

    int qt = blockIdx.x, h = blockIdx.y, b = blockIdx.z;
    int tid = threadIdx.x;
    int wid = tid >> 5, lane = tid & 31;
    int wm = (wid & 3) * 32;           // 4 warps over 128 rows
    int wn = (wid >> 2) * 32;          // 2 warps over 64 cols
    const int qcol = 1024 + h * HD;
    const int kcol = 1536 + h * HD;
    const int vcol = 512 + h * HD;
    uint32_t aoff = ldm_off(lane, SAT);

    // Load Q tile (128 x 64), plain float4
#pragma unroll
    for (int i = 0; i < 8; i++) {
        int idx = tid + i * 256;           // 2048 float4 slots
        int row = idx >> 4, seg = idx & 15;
        float4 v = *(const float4*)(g_mm + (size_t)(b * NN + qt * 128 + row) * NC + qcol + seg * 4);
        *(float4*)(Qs + row * SAT + seg * 4) = v;
    }

    // cp.async stage of K and V kv-tile kt into buffer s
    auto stageKV = [&](int kt, int s) {
        uint32_t kd = sbase + OFF_K + s * KTILE;
        uint32_t vd = sbase + OFF_V + s * KTILE;
#pragma unroll
        for (int i = 0; i < 4; i++) {
            int idx = tid + i * 256;       // 1024 segs each
            int row = idx >> 4, seg = idx & 15;
            size_t gb = (size_t)(b * NN + kt * 64 + row) * NC;
            uint32_t so = (uint32_t)((row * SAT + seg * 4) * 4);
            cp16(kd + so, g_mm + gb + kcol + seg * 4);
            cp16(vd + so, g_mm + gb + vcol + seg * 4);
        }
    };

    float oacc[2][4][4];
#pragma unroll
    for (int i = 0; i < 2; i++)
#pragma unroll
        for (int j = 0; j < 4; j++)
#pragma unroll
            for (int r = 0; r < 4; r++) oacc[i][j][r] = 0.0f;

    const float inv_n = 1.0f / (float)NN;
    int er = lane >> 2, ec = (lane & 3) * 2;
    const int nkt = 2 * qt + 2;

    stageKV(0, 0); CP_COMMIT();

    for (int kt = 0; kt < nkt; kt++) {
        int s = kt & 1;
        __syncthreads();     // all reads of buffer s (iter kt-2) and Ss done
        if (kt + 1 < nkt) {
            stageKV(kt + 1, s ^ 1); CP_COMMIT();
            CP_WAIT(1);
        } else {
            CP_WAIT(0);
        }
        __syncthreads();

        const float* Ksf = (const float*)(smem + OFF_K + s * KTILE);
        const float* Vsf = (const float*)(smem + OFF_V + s * KTILE);

        // Phase 1: S = Q @ K^T  (b0 = Ks[n_seq][k_d])
        float sacc[2][4][4];
#pragma unroll
        for (int i = 0; i < 2; i++)
#pragma unroll
            for (int j = 0; j < 4; j++)
#pragma unroll
                for (int r = 0; r < 4; r++) sacc[i][j][r] = 0.0f;
#pragma unroll
        for (int ks = 0; ks < 8; ks++) {
            uint32_t bf[4][2];
#pragma unroll
            for (int in = 0; in < 4; in++) {
                int nn = wn + in * 8 + lane / 4;
                int kk = ks * 8 + (lane & 3);
                bf[in][0] = __float_as_uint(Ksf[nn * SAT + kk]);
                bf[in][1] = __float_as_uint(Ksf[nn * SAT + kk + 4]);
            }
#pragma unroll
            for (int im = 0; im < 2; im++) {
                uint32_t a[4];
                ldmA(a, Qsu + (uint32_t)(((wm + im * 16) * SAT + ks * 8) * 4) + aoff);
#pragma unroll
                for (int in = 0; in < 4; in++)
                    mma_tf32(sacc[im][in], a, bf[in][0], bf[in][1]);
            }
        }

        // silu/N + causal mask -> Ss
        bool need_mask = (kt >= 2 * qt);
        int jbase = kt * 64, ibase = qt * 128;
#pragma unroll
        for (int im = 0; im < 2; im++) {
#pragma unroll
            for (int in = 0; in < 4; in++) {
#pragma unroll
                for (int hh = 0; hh < 2; hh++) {
                    int i = wm + im * 16 + er + 8 * hh;
                    int j = wn + in * 8 + ec;
                    float v0 = silu_f(sacc[im][in][2 * hh + 0]) * inv_n;
                    float v1 = silu_f(sacc[im][in][2 * hh + 1]) * inv_n;
                    if (need_mask) {
                        int ig = ibase + i, jg = jbase + j;
                        if (jg > ig) v0 = 0.0f;
                        if (jg + 1 > ig) v1 = 0.0f;
                    }
                    float2 o; o.x = v0; o.y = v1;
                    *(float2*)(Ss + i * SAT + j) = o;
                }
            }
        }
        __syncthreads();

        // Phase 2: O += S @ V  (b0 = Vs[k_seq][n_d])
#pragma unroll
        for (int ks = 0; ks < 8; ks++) {
            uint32_t bf[4][2];
#pragma unroll
            for (int in = 0; in < 4; in++) {
                int nn = wn + in * 8 + lane / 4;
                int kk = ks * 8 + (lane & 3);
                bf[in][0] = __float_as_uint(Vsf[kk * SAT + nn]);
                bf[in][1] = __float_as_uint(Vsf[(kk + 4) * SAT + nn]);
            }
#pragma unroll
            for (int im = 0; im < 2; im++) {
                uint32_t a[4];
                ldmA(a, Ssu + (uint32_t)(((wm + im * 16) * SAT + ks * 8) * 4) + aoff);
#pragma unroll
                for (int in = 0; in < 4; in++)
                    mma_tf32(oacc[im][in], a, bf[in][0], bf[in][1]);
            }
        }
    }

    // Write O tile (128 rows x 64 cols) to g_at
#pragma unroll
    for (int im = 0; im < 2; im++) {
#pragma unroll
        for (int in = 0; in < 4; in++) {
#pragma unroll
            for (int hh = 0; hh < 2; hh++) {
                int n = qt * 128 + wm + im * 16 + er + 8 * hh;
                int j = h * HD + wn + in * 8 + ec;
                float2 o;
                o.x = oacc[im][in][2 * hh + 0];
                o.y = oacc[im][in][2 * hh + 1];
                *(float2*)(g_at + (size_t)(b * NN + n) * DD + j) = o;
            }
        }
    }
}

// ---------------------------------------------------------------------------
extern "C" void kernel_launch(void* const* d_in, const int* in_sizes, int n_in,
                              void* d_out, int out_size) {
    const float* x    = (const float*)d_in[0];
    const float* uvqk = (const float*)d_in[2];
    const float* ow   = (const float*)d_in[3];
    const float* ob   = (const float*)d_in[4];
    float* out = (float*)d_out;

    void *pxn, *pmm;
    cudaGetSymbolAddress(&pxn, g_xn);
    cudaGetSymbolAddress(&pmm, g_mm);

    cudaFuncSetAttribute(gemm_mma<0>, cudaFuncAttributeMaxDynamicSharedMemorySize, GSMEM);
    cudaFuncSetAttribute(gemm_mma<1>, cudaFuncAttributeMaxDynamicSharedMemorySize, GSMEM);
    cudaFuncSetAttribute(attn_mma, cudaFuncAttributeMaxDynamicSharedMemorySize, ASMEM);

    // 1. xn = layernorm(x)
    ln_kernel<<<RR, 128>>>(x);
    // 2. mm = silu(xn @ uvqk)  [8192 x 2048, K=512]
    gemm_mma<0><<<dim3(NC / 128, RR / 128), 256, GSMEM>>>(
        (const float*)pxn, uvqk, (float*)pmm, nullptr, nullptr, NC, DD);
    // 3. attention (q-tiles of 128 rows)
    attn_mma<<<dim3(NN / 128, HH, BB), 256, ASMEM>>>();
    // 4. o_input = u * layernorm(attn) -> g_xn
    gated_ln_kernel<<<RR, 128>>>();
    // 5. out = o_input @ o_weight^T + bias + x  [8192 x 512, K=512]
    gemm_mma<1><<<dim3(DD / 128, RR / 128), 256, GSMEM>>>(
        (const float*)pxn, ow, out, ob, x, DD, DD);
}